// round 8
// baseline (speedup 1.0000x reference)
#include <cuda_runtime.h>
#include <mma.h>
using namespace nvcuda;

// ---------------- problem constants ----------------
#define BB    64      // batch
#define NSP   49      // spatial positions
#define ENC   1024
#define DEC   512
#define EMBD  512
#define VOC   10000
#define MSN   8       // max sentences
#define MWN   20      // max words
#define BW    512     // MSN*BB : batched word-RNN rows
#define G3    1536    // 3*DEC
#define NCMB  2048    // G3 + EMBD : fused ghw|att2 output width

// ---------------- device scratch (static, no allocation) ----------------
__device__ float d_gf   [BB * ENC];
__device__ float d_hs   [BB * DEC];
__device__ float d_gis  [BB * G3];
__device__ float d_ghs  [BB * G3];
__device__ float d_HS   [MSN * BB * DEC];
__device__ float d_att1 [BB * NSP * EMBD];
__device__ float d_EMBT [MWN * BW * EMBD];
__device__ float d_EMBGI[MWN * BW * G3];
__device__ float d_H    [BW * DEC];
__device__ float d_Hall [MWN * BW * DEC];
__device__ float d_gha  [BW * NCMB];     // [ghw(1536) | att2(512)] per row
__device__ float d_ctx  [BW * ENC];
__device__ float d_gictx[BW * G3];
__device__ float d_Wcmb [NCMB * DEC];    // concat(w_W_hh, att_dec_W)
__device__ float d_bcmb [NCMB];

// ================= tf32 tensor-core GEMM v2: C = A @ W^T + bias ==============
// 256 threads, block tile 128x128, warp tile 32x64 (2x4 frags of 16x16x8).
// Double-buffered smem + register prefetch. RNA tf32 rounding at commit.
// K % 32 == 0.
#define SLD   36                         // smem row stride (floats)
#define STAGE (128 * SLD * 2)            // A + W one stage = 9216 floats
#define CLD   132
#define MMA2_SMEM_BYTES (2 * STAGE * 4)  // 73728 B (Cs 128*132=16896 fits)

__global__ void __launch_bounds__(256)
mma2(const float* __restrict__ A, int lda,
     const float* __restrict__ W, int ldw,
     const float* __restrict__ bias,
     float* __restrict__ C, int ldc,
     int M, int N, int K)
{
    extern __shared__ float sm[];

    const int tid  = threadIdx.x;
    const int warp = tid >> 5;
    const int wm   = warp >> 1;          // 0..3
    const int wn   = warp & 1;           // 0..1
    const int m0   = blockIdx.x * 128;
    const int n0   = blockIdx.y * 128;

    const int ldr  = tid >> 1;           // 0..127
    const int ldc0 = (tid & 1) * 16;     // 0 or 16

    const bool am = (m0 + ldr) < M;
    const bool wv = (n0 + ldr) < N;
    const float* Arow = A + (size_t)(m0 + ldr) * lda + ldc0;
    const float* Wrow = W + (size_t)(n0 + ldr) * ldw + ldc0;

    wmma::fragment<wmma::accumulator, 16, 16, 8, float> acc[2][4];
#pragma unroll
    for (int i = 0; i < 2; i++)
#pragma unroll
        for (int j = 0; j < 4; j++)
            wmma::fill_fragment(acc[i][j], 0.0f);

    float4 ra[4], rw[4];
    const float4 z4 = make_float4(0.f, 0.f, 0.f, 0.f);

#define FETCH(k0)                                                         \
    {                                                                     \
        _Pragma("unroll")                                                 \
        for (int j = 0; j < 4; j++) {                                     \
            ra[j] = am ? *(const float4*)(Arow + (k0) + 4 * j) : z4;      \
            rw[j] = wv ? *(const float4*)(Wrow + (k0) + 4 * j) : z4;      \
        }                                                                 \
    }

#define COMMIT(s)                                                         \
    {                                                                     \
        float* as_ = sm + (s) * STAGE;                                    \
        float* ws_ = as_ + 128 * SLD;                                     \
        _Pragma("unroll")                                                 \
        for (int j = 0; j < 4; j++) {                                     \
            float4 v = ra[j];                                             \
            v.x = wmma::__float_to_tf32(v.x); v.y = wmma::__float_to_tf32(v.y); \
            v.z = wmma::__float_to_tf32(v.z); v.w = wmma::__float_to_tf32(v.w); \
            *(float4*)(as_ + ldr * SLD + ldc0 + 4 * j) = v;               \
            v = rw[j];                                                    \
            v.x = wmma::__float_to_tf32(v.x); v.y = wmma::__float_to_tf32(v.y); \
            v.z = wmma::__float_to_tf32(v.z); v.w = wmma::__float_to_tf32(v.w); \
            *(float4*)(ws_ + ldr * SLD + ldc0 + 4 * j) = v;               \
        }                                                                 \
    }

    FETCH(0); COMMIT(0); __syncthreads();

    int buf = 0;
    for (int k0 = 0; k0 < K; k0 += 32) {
        const bool more = (k0 + 32) < K;
        if (more) FETCH(k0 + 32);

        const float* as_ = sm + buf * STAGE;
        const float* ws_ = as_ + 128 * SLD;
#pragma unroll
        for (int kk = 0; kk < 32; kk += 8) {
            wmma::fragment<wmma::matrix_a, 16, 16, 8, wmma::precision::tf32, wmma::row_major> af[2];
            wmma::fragment<wmma::matrix_b, 16, 16, 8, wmma::precision::tf32, wmma::col_major> bf[4];
#pragma unroll
            for (int i = 0; i < 2; i++)
                wmma::load_matrix_sync(af[i], as_ + (wm * 32 + i * 16) * SLD + kk, SLD);
#pragma unroll
            for (int j = 0; j < 4; j++)
                wmma::load_matrix_sync(bf[j], ws_ + (wn * 64 + j * 16) * SLD + kk, SLD);
#pragma unroll
            for (int i = 0; i < 2; i++)
#pragma unroll
                for (int j = 0; j < 4; j++)
                    wmma::mma_sync(acc[i][j], af[i], bf[j], acc[i][j]);
        }

        if (more) COMMIT(buf ^ 1);
        __syncthreads();
        buf ^= 1;
    }

    // epilogue: stage C in smem, bias-add, vectorized write
    float* Cs = sm;
#pragma unroll
    for (int i = 0; i < 2; i++)
#pragma unroll
        for (int j = 0; j < 4; j++)
            wmma::store_matrix_sync(Cs + (wm * 32 + i * 16) * CLD + wn * 64 + j * 16,
                                    acc[i][j], CLD, wmma::mem_row_major);
    __syncthreads();

    const int r  = tid >> 1;
    const int ch = (tid & 1) * 64;
    const int gm = m0 + r;
    if (gm < M) {
        float* crow = C + (size_t)gm * ldc;
#pragma unroll
        for (int c = 0; c < 64; c += 4) {
            int gn = n0 + ch + c;
            if (gn + 3 < N) {
                float4 v = *(float4*)(Cs + r * CLD + ch + c);
                if (bias) {
                    v.x += bias[gn + 0]; v.y += bias[gn + 1];
                    v.z += bias[gn + 2]; v.w += bias[gn + 3];
                }
                *(float4*)(crow + gn) = v;
            } else {
                for (int u = 0; u < 4; u++)
                    if (gn + u < N)
                        crow[gn + u] = Cs[r * CLD + ch + c + u] + (bias ? bias[gn + u] : 0.f);
            }
        }
    }
#undef FETCH
#undef COMMIT
}

// ======= warp-cooperative skinny GEMM (M=64): C = act(A @ W^T + bias) =======
// Each warp computes a 2(m) x 8(n) patch; A rows cached in registers,
// W rows streamed coalesced, shfl-bfly reduction. K in {512, 1024}.
template <int ACT>   // 0 = none, 1 = tanh
__global__ void __launch_bounds__(256)
skinny2(const float* __restrict__ A, const float* __restrict__ W,
        const float* __restrict__ bias, float* __restrict__ C,
        int N, int K)
{
    const int warp = (blockIdx.x << 3) + (threadIdx.x >> 5);
    const int lane = threadIdx.x & 31;
    const int ntil = N >> 3;
    const int mt = warp / ntil;
    const int nt = warp - mt * ntil;
    if (mt >= 32) return;
    const int m0 = mt * 2, n0 = nt * 8;

    const int nch = K >> 7;              // chunks of 32 float4 (4 @K=512, 8 @K=1024)
    const float4* A0 = (const float4*)(A + (size_t)m0 * K);
    const float4* A1 = (const float4*)(A + (size_t)(m0 + 1) * K);
    float4 a0[8], a1[8];
#pragma unroll
    for (int i = 0; i < 8; i++) {
        if (i < nch) { a0[i] = A0[lane + 32 * i]; a1[i] = A1[lane + 32 * i]; }
    }

#pragma unroll
    for (int n = 0; n < 8; n++) {
        const float4* Wr = (const float4*)(W + (size_t)(n0 + n) * K);
        float s0 = 0.f, s1 = 0.f;
#pragma unroll
        for (int i = 0; i < 8; i++) {
            if (i < nch) {
                float4 w = Wr[lane + 32 * i];
                s0 += a0[i].x * w.x + a0[i].y * w.y + a0[i].z * w.z + a0[i].w * w.w;
                s1 += a1[i].x * w.x + a1[i].y * w.y + a1[i].z * w.z + a1[i].w * w.w;
            }
        }
#pragma unroll
        for (int o = 16; o; o >>= 1) {
            s0 += __shfl_xor_sync(0xffffffff, s0, o);
            s1 += __shfl_xor_sync(0xffffffff, s1, o);
        }
        if (lane == n) {
            float b = bias[n0 + n];
            s0 += b; s1 += b;
            if (ACT == 1) { s0 = tanhf(s0); s1 = tanhf(s1); }
            C[(size_t)m0 * N + n0 + n]       = s0;
            C[(size_t)(m0 + 1) * N + n0 + n] = s1;
        }
    }
}

// ---------------- small kernels ----------------
__global__ void mean_kernel(const float* __restrict__ sp)
{
    int b = blockIdx.x;
    for (int e = threadIdx.x; e < ENC; e += blockDim.x) {
        float s = 0.f;
        for (int n = 0; n < NSP; n++) s += sp[((size_t)b * NSP + n) * ENC + e];
        d_gf[b * ENC + e] = s * (1.0f / 49.0f);
    }
}

__global__ void concat_w(const float* __restrict__ whh, const float* __restrict__ wdec,
                         const float* __restrict__ bhh, const float* __restrict__ bdec)
{
    int i = blockIdx.x * 256 + threadIdx.x;
    if (i < NCMB * DEC) {
        int r = i >> 9, c = i & 511;
        d_Wcmb[i] = (r < G3) ? whh[i] : wdec[(size_t)(r - G3) * DEC + c];
    }
    if (i < NCMB) d_bcmb[i] = (i < G3) ? bhh[i] : bdec[i - G3];
}

__device__ __forceinline__ float sigmf(float x) { return 1.0f / (1.0f + expf(-x)); }

__global__ void sgru_gate(int i)
{
    int b = blockIdx.x, j = threadIdx.x;
    float gr = d_gis[b * G3 + j]            + d_ghs[b * G3 + j];
    float gz = d_gis[b * G3 + DEC + j]      + d_ghs[b * G3 + DEC + j];
    float gni = d_gis[b * G3 + 2 * DEC + j];
    float gnh = d_ghs[b * G3 + 2 * DEC + j];
    float h  = d_hs[b * DEC + j];
    float r  = sigmf(gr);
    float z  = sigmf(gz);
    float n  = tanhf(gni + r * gnh);
    float hn = (1.0f - z) * n + z * h;
    d_hs[b * DEC + j] = hn;
    d_HS[(size_t)i * BB * DEC + b * DEC + j] = hn;
}

__global__ void policy_stop_kernel(const float* __restrict__ pW, const float* __restrict__ pb,
                                   const float* __restrict__ sW, const float* __restrict__ sb,
                                   float* __restrict__ out)
{
    int row = blockIdx.x;            // i*BB + b (HS row)
    int i = row >> 6, b = row & 63;
    int warp = threadIdx.x >> 5, lane = threadIdx.x & 31;
    const float* h = d_HS + (size_t)row * DEC;
    const float* w = (warp < 5) ? (pW + warp * DEC) : sW;
    float s = 0.f;
    for (int k = lane; k < DEC; k += 32) s += h[k] * w[k];
#pragma unroll
    for (int o = 16; o; o >>= 1) s += __shfl_xor_sync(0xffffffff, s, o);
    if (lane == 0) {
        if (warp < 5) out[(b * MSN + i) * 5 + warp] = s + pb[warp];
        else          out[BB * MSN * 5 + b * MSN + i] = s + sb[0];
    }
}

__global__ void gather_emb(const int* __restrict__ tw, const float* __restrict__ embW)
{
    int idx = blockIdx.x * blockDim.x + threadIdx.x;
    const int total = MWN * BW * (EMBD / 4);        // 1,310,720
    if (idx >= total) return;
    int c4 = idx & 127;
    int r  = (idx >> 7) & 511;
    int t  = idx >> 16;
    int b = r & 63, s = r >> 6;
    int w = (t == 0) ? 1 : tw[b * MSN * MWN + s * MWN + (t - 1)];
    float4 v = *(const float4*)(embW + (size_t)w * EMBD + c4 * 4);
    *(float4*)(&d_EMBT[((size_t)t * BW + r) * EMBD + c4 * 4]) = v;
}

__global__ void copyH_kernel()
{
    int i = blockIdx.x * blockDim.x + threadIdx.x;
    d_H[i] = d_HS[i];
}

// attention: e = relu(att1[b] + att2[r]) . wfull + bf ; softmax; ctx
// att2 lives in d_gha[r*NCMB + G3 ..]
__global__ void __launch_bounds__(256)
attn_kernel(const float* __restrict__ sp,
            const float* __restrict__ wfull, const float* __restrict__ bfull)
{
    __shared__ float a2[EMBD];
    __shared__ float e[64];
    __shared__ float alpha[64];

    int r = blockIdx.x;
    int b = r & (BB - 1);
    int tid = threadIdx.x;
    int warp = tid >> 5, lane = tid & 31;

    for (int k = tid; k < EMBD; k += 256) a2[k] = d_gha[(size_t)r * NCMB + G3 + k];
    __syncthreads();

    for (int n = warp; n < NSP; n += 8) {
        const float* a1 = d_att1 + ((size_t)(b * NSP + n)) * EMBD;
        float s = 0.f;
        for (int k = lane; k < EMBD; k += 32) {
            float v = a1[k] + a2[k];
            v = fmaxf(v, 0.f);
            s += v * wfull[k];
        }
#pragma unroll
        for (int o = 16; o; o >>= 1) s += __shfl_xor_sync(0xffffffff, s, o);
        if (lane == 0) e[n] = s + bfull[0];
    }
    __syncthreads();

    if (warp == 0) {
        float m = -1e30f;
        for (int n = lane; n < NSP; n += 32) m = fmaxf(m, e[n]);
#pragma unroll
        for (int o = 16; o; o >>= 1) m = fmaxf(m, __shfl_xor_sync(0xffffffff, m, o));
        float ssum = 0.f;
        for (int n = lane; n < NSP; n += 32) { float t = expf(e[n] - m); alpha[n] = t; ssum += t; }
#pragma unroll
        for (int o = 16; o; o >>= 1) ssum += __shfl_xor_sync(0xffffffff, ssum, o);
        float inv = 1.0f / ssum;
        for (int n = lane; n < NSP; n += 32) alpha[n] *= inv;
    }
    __syncthreads();

    for (int c = tid; c < ENC; c += 256) {
        float s = 0.f;
#pragma unroll 7
        for (int n = 0; n < NSP; n++) s += alpha[n] * sp[((size_t)(b * NSP + n)) * ENC + c];
        d_ctx[(size_t)r * ENC + c] = s;
    }
}

__global__ void wgru_gate(int t)
{
    int r = blockIdx.x, j = threadIdx.x;
    size_t eb = ((size_t)t * BW + r) * G3;
    size_t rb = (size_t)r * G3;
    size_t gb = (size_t)r * NCMB;
    float gir = d_EMBGI[eb + j]           + d_gictx[rb + j];
    float giz = d_EMBGI[eb + DEC + j]     + d_gictx[rb + DEC + j];
    float gin = d_EMBGI[eb + 2 * DEC + j] + d_gictx[rb + 2 * DEC + j];
    float ghr = d_gha[gb + j];
    float ghz = d_gha[gb + DEC + j];
    float ghn = d_gha[gb + 2 * DEC + j];
    float h   = d_H[(size_t)r * DEC + j];
    float rg = sigmf(gir + ghr);
    float z  = sigmf(giz + ghz);
    float n  = tanhf(gin + rg * ghn);
    float hn = (1.0f - z) * n + z * h;
    d_H[(size_t)r * DEC + j] = hn;
    int b = r & 63, s = r >> 6;
    d_Hall[((size_t)((b * MSN + s) * MWN + t)) * DEC + j] = hn;
}

// ---------------- cached scratch addresses ----------------
static float *gf, *hs, *gis, *ghs, *att1, *embt, *embgi, *H, *Hall,
             *gha, *ctx, *gictx, *Wcmb, *bcmb;
static bool g_init = false;

static void resolve_scratch()
{
    cudaGetSymbolAddress((void**)&gf,    d_gf);
    cudaGetSymbolAddress((void**)&hs,    d_hs);
    cudaGetSymbolAddress((void**)&gis,   d_gis);
    cudaGetSymbolAddress((void**)&ghs,   d_ghs);
    cudaGetSymbolAddress((void**)&att1,  d_att1);
    cudaGetSymbolAddress((void**)&embt,  d_EMBT);
    cudaGetSymbolAddress((void**)&embgi, d_EMBGI);
    cudaGetSymbolAddress((void**)&H,     d_H);
    cudaGetSymbolAddress((void**)&Hall,  d_Hall);
    cudaGetSymbolAddress((void**)&gha,   d_gha);
    cudaGetSymbolAddress((void**)&ctx,   d_ctx);
    cudaGetSymbolAddress((void**)&gictx, d_gictx);
    cudaGetSymbolAddress((void**)&Wcmb,  d_Wcmb);
    cudaGetSymbolAddress((void**)&bcmb,  d_bcmb);
    cudaFuncSetAttribute(mma2, cudaFuncAttributeMaxDynamicSharedMemorySize,
                         MMA2_SMEM_BYTES);
    g_init = true;
}

// ---------------- host launcher ----------------
extern "C" void kernel_launch(void* const* d_in, const int* in_sizes, int n_in,
                              void* d_out, int out_size)
{
    if (!g_init) resolve_scratch();

    const float* spatial    = (const float*)d_in[0];
    const int*   tw         = (const int*)  d_in[1];
    const float* emb_W      = (const float*)d_in[2];
    const float* s_W_ih     = (const float*)d_in[3];
    const float* s_W_hh     = (const float*)d_in[4];
    const float* s_b_ih     = (const float*)d_in[5];
    const float* s_b_hh     = (const float*)d_in[6];
    const float* policy_W   = (const float*)d_in[7];
    const float* policy_b   = (const float*)d_in[8];
    const float* stop_W     = (const float*)d_in[9];
    const float* stop_b     = (const float*)d_in[10];
    const float* att_enc_W  = (const float*)d_in[11];
    const float* att_enc_b  = (const float*)d_in[12];
    const float* att_dec_W  = (const float*)d_in[13];
    const float* att_dec_b  = (const float*)d_in[14];
    const float* att_full_W = (const float*)d_in[15];
    const float* att_full_b = (const float*)d_in[16];
    const float* w_W_ih     = (const float*)d_in[17];
    const float* w_W_hh     = (const float*)d_in[18];
    const float* w_b_ih     = (const float*)d_in[19];
    const float* w_b_hh     = (const float*)d_in[20];
    const float* fc_W       = (const float*)d_in[21];
    const float* fc_b       = (const float*)d_in[22];
    const float* init_W     = (const float*)d_in[23];
    const float* init_b     = (const float*)d_in[24];
    float* out = (float*)d_out;

    // ---- setup ----
    mean_kernel<<<BB, 256>>>(spatial);
    concat_w<<<(NCMB * DEC + 255) / 256, 256>>>(w_W_hh, att_dec_W, w_b_hh, att_dec_b);
    // h0 = tanh(gf @ init_W.T + init_b)
    skinny2<1><<<32 * (DEC / 8) / 8, 256>>>(gf, init_W, init_b, hs, DEC, ENC);
    // att1 = spatial @ att_enc_W.T + att_enc_b  (M=3136: edge tile handled)
    mma2<<<dim3((BB * NSP + 127) / 128, EMBD / 128), 256, MMA2_SMEM_BYTES>>>(
        spatial, ENC, att_enc_W, ENC, att_enc_b, att1, EMBD, BB * NSP, EMBD, ENC);
    // gi_s constant across sentence steps
    skinny2<0><<<32 * (G3 / 8) / 8, 256>>>(gf, s_W_ih, s_b_ih, gis, G3, ENC);

    // ---- sentence GRU: 8 tiny sequential steps ----
    for (int i = 0; i < MSN; i++) {
        skinny2<0><<<32 * (G3 / 8) / 8, 256>>>(hs, s_W_hh, s_b_hh, ghs, G3, DEC);
        sgru_gate<<<BB, DEC>>>(i);
    }
    policy_stop_kernel<<<MSN * BB, 192>>>(policy_W, policy_b, stop_W, stop_b, out);

    // ---- batched precomputes for word RNN ----
    gather_emb<<<(MWN * BW * (EMBD / 4) + 255) / 256, 256>>>(tw, emb_W);
    mma2<<<dim3(MWN * BW / 128, G3 / 128), 256, MMA2_SMEM_BYTES>>>(
        embt, EMBD, w_W_ih, EMBD + ENC, w_b_ih, embgi, G3, MWN * BW, G3, EMBD);
    copyH_kernel<<<512, 512>>>();   // H init = HS (identical layout)

    // ---- word RNN: 20 sequential steps over 512 batched rows ----
    const dim3 gCMB(BW / 128, NCMB / 128);   // (4, 16)
    const dim3 gG3 (BW / 128, G3 / 128);     // (4, 12)
    for (int t = 0; t < MWN; t++) {
        // [ghw | att2] = H @ [W_hh ; att_dec_W]^T + [b_hh ; att_dec_b]
        mma2<<<gCMB, 256, MMA2_SMEM_BYTES>>>(H, DEC, Wcmb, DEC, bcmb,
                                             gha, NCMB, BW, NCMB, DEC);
        attn_kernel<<<BW, 256>>>(spatial, att_full_W, att_full_b);
        mma2<<<gG3, 256, MMA2_SMEM_BYTES>>>(ctx, ENC, w_W_ih + EMBD, EMBD + ENC,
                                            (const float*)nullptr, gictx, G3, BW, G3, ENC);
        wgru_gate<<<BW, DEC>>>(t);
    }

    // ---- final vocab projection straight into the output ----
    mma2<<<dim3(MWN * BW / 128, (VOC + 127) / 128), 256, MMA2_SMEM_BYTES>>>(
        Hall, DEC, fc_W, DEC, fc_b, out + 3072, VOC, MWN * BW, VOC, DEC);
}